// round 9
// baseline (speedup 1.0000x reference)
#include <cuda_runtime.h>
#include <cuda_bf16.h>
#include <mma.h>
#include <math.h>
#include <stdint.h>

using namespace nvcuda;

// Problem constants
#define NB 16
#define T1 400
#define T2 600
#define DIM 1024
#define NDIAG (T1 + T2 - 1)   // 999
#define T2Q (T2 / 4)          // 150 packed-choice bytes per row
#define SPLIT 192             // DTW backtrack staging split row

// ---------------------------------------------------------------------------
// Device scratch (no allocations allowed)
// ---------------------------------------------------------------------------
__device__ float g_Dd[NB * NDIAG * T1];        // distance matrix, diag-major [b][k][i]
__device__ float g_na[NB * T1];
__device__ float g_nb[NB * T2];
__device__ int   g_lo[NB * T2];
__device__ int   g_hi[NB * T2];
__device__ unsigned char g_ch[NB * T2Q * T1];  // 2-bit DP choices [b][jq][i]

// ---------------------------------------------------------------------------
// Kernel 0: dummies — keep the ncu-profiled launch slot on the GEMM.
// ---------------------------------------------------------------------------
__global__ void dummy_kernel() {}

// ---------------------------------------------------------------------------
// Kernel 1: squared norms. One warp per row.
// ---------------------------------------------------------------------------
__global__ void norm_kernel(const float* __restrict__ T, const float* __restrict__ S) {
    int warp = (blockIdx.x * blockDim.x + threadIdx.x) >> 5;
    int lane = threadIdx.x & 31;
    const int NT = NB * T1;
    const int NS = NB * T2;
    if (warp >= NT + NS) return;
    const float* src;
    float* dst;
    if (warp < NT) { src = T + (size_t)warp * DIM;        dst = g_na + warp; }
    else           { src = S + (size_t)(warp - NT) * DIM; dst = g_nb + (warp - NT); }
    float s = 0.f;
#pragma unroll
    for (int it = 0; it < DIM / 128; it++) {
        float4 v = *(const float4*)(src + (size_t)(lane + it * 32) * 4);
        s += v.x * v.x + v.y * v.y + v.z * v.z + v.w * v.w;
    }
#pragma unroll
    for (int o = 16; o; o >>= 1) s += __shfl_xor_sync(0xFFFFFFFFu, s, o);
    if (lane == 0) *dst = s;
}

// ---------------------------------------------------------------------------
// Kernel 2: WMMA tf32 batched GEMM (2x split, 3 products) + distance epilogue
// -> diagonal-major D.  BM=BN=128, BK=8, 256 threads / 8 warps (2m x 4n),
// warp tile 64x32 = 4x2 m16n16k8 wmma tiles. Double-buffered hi/lo smem.
// No inline asm anywhere — pure nvcuda::wmma.
// ---------------------------------------------------------------------------
#define BM 128
#define BN 128
#define BK 8
#define NKT (DIM / BK)   // 128
#define SP 136           // padded row

__global__ __launch_bounds__(256)
void gemm_dist_kernel(const float* __restrict__ A, const float* __restrict__ B) {
    __shared__ float As[2][2][BK][SP];   // [buf][hi/lo][k][m]  17408 B
    __shared__ float Bs[2][2][BK][SP];   // [buf][hi/lo][k][n]  17408 B
    __shared__ float patch[8][256];      // per-warp accumulator staging, 8 KB

    int b  = blockIdx.z;
    int m0 = blockIdx.y * BM;
    int n0 = blockIdx.x * BN;
    const float* Ab = A + (size_t)b * T1 * DIM;
    const float* Bb = B + (size_t)b * T2 * DIM;

    int tid  = threadIdx.x;
    int wid  = tid >> 5;
    int lane = tid & 31;
    int wm = wid >> 2;        // 0..1 (m offset wm*64)
    int wn = wid & 3;         // 0..3 (n offset wn*32)

    wmma::fragment<wmma::accumulator, 16, 16, 8, float> cfrag[4][2];
#pragma unroll
    for (int mt = 0; mt < 4; mt++)
#pragma unroll
        for (int nt = 0; nt < 2; nt++)
            wmma::fill_fragment(cfrag[mt][nt], 0.f);

    // Loader: 256 threads, each one float4 of A and one of B per stage.
    int row  = tid >> 1;            // 0..127
    int col4 = (tid & 1) * 4;       // 0 or 4
    bool aok = (m0 + row) < T1;
    bool bok = (n0 + row) < T2;
    const float* aptr = Ab + (size_t)(m0 + row) * DIM + col4;
    const float* bptr = Bb + (size_t)(n0 + row) * DIM + col4;

    const float4 Z = make_float4(0.f, 0.f, 0.f, 0.f);
    float4 va, vb;

    // stage 0
    va = aok ? *(const float4*)(aptr) : Z;
    vb = bok ? *(const float4*)(bptr) : Z;
    {
        float f[4] = { va.x, va.y, va.z, va.w };
        float h[4] = { vb.x, vb.y, vb.z, vb.w };
#pragma unroll
        for (int jj = 0; jj < 4; jj++) {
            float hi = wmma::__float_to_tf32(f[jj]);
            float lo = wmma::__float_to_tf32(f[jj] - hi);
            As[0][0][col4 + jj][row] = hi;
            As[0][1][col4 + jj][row] = lo;
            hi = wmma::__float_to_tf32(h[jj]);
            lo = wmma::__float_to_tf32(h[jj] - hi);
            Bs[0][0][col4 + jj][row] = hi;
            Bs[0][1][col4 + jj][row] = lo;
        }
    }
    __syncthreads();

    for (int kt = 0; kt < NKT; kt++) {
        int buf = kt & 1;
        if (kt + 1 < NKT) {
            va = aok ? *(const float4*)(aptr + (kt + 1) * BK) : Z;
            vb = bok ? *(const float4*)(bptr + (kt + 1) * BK) : Z;
        }

        // A fragments: col_major (element (m,k) at As[..][k][m], ldm = SP)
        wmma::fragment<wmma::matrix_a, 16, 16, 8, wmma::precision::tf32, wmma::col_major> a_hi[4], a_lo[4];
#pragma unroll
        for (int mt = 0; mt < 4; mt++) {
            wmma::load_matrix_sync(a_hi[mt], &As[buf][0][0][wm * 64 + mt * 16], SP);
            wmma::load_matrix_sync(a_lo[mt], &As[buf][1][0][wm * 64 + mt * 16], SP);
        }
        // B fragments: row_major (element (k,n) at Bs[..][k][n], ldm = SP)
        wmma::fragment<wmma::matrix_b, 16, 16, 8, wmma::precision::tf32, wmma::row_major> b_hi[2], b_lo[2];
#pragma unroll
        for (int nt = 0; nt < 2; nt++) {
            wmma::load_matrix_sync(b_hi[nt], &Bs[buf][0][0][wn * 32 + nt * 16], SP);
            wmma::load_matrix_sync(b_lo[nt], &Bs[buf][1][0][wn * 32 + nt * 16], SP);
        }

#pragma unroll
        for (int mt = 0; mt < 4; mt++)
#pragma unroll
            for (int nt = 0; nt < 2; nt++) {
                wmma::mma_sync(cfrag[mt][nt], a_hi[mt], b_lo[nt], cfrag[mt][nt]);  // hi*lo
                wmma::mma_sync(cfrag[mt][nt], a_lo[mt], b_hi[nt], cfrag[mt][nt]);  // lo*hi
                wmma::mma_sync(cfrag[mt][nt], a_hi[mt], b_hi[nt], cfrag[mt][nt]);  // hi*hi
            }

        if (kt + 1 < NKT) {
            int nbuf = buf ^ 1;
            float f[4] = { va.x, va.y, va.z, va.w };
            float h[4] = { vb.x, vb.y, vb.z, vb.w };
#pragma unroll
            for (int jj = 0; jj < 4; jj++) {
                float hi = wmma::__float_to_tf32(f[jj]);
                float lo = wmma::__float_to_tf32(f[jj] - hi);
                As[nbuf][0][col4 + jj][row] = hi;
                As[nbuf][1][col4 + jj][row] = lo;
                hi = wmma::__float_to_tf32(h[jj]);
                lo = wmma::__float_to_tf32(h[jj] - hi);
                Bs[nbuf][0][col4 + jj][row] = hi;
                Bs[nbuf][1][col4 + jj][row] = lo;
            }
            __syncthreads();
        }
    }

    // Epilogue: stage each 16x16 frag to smem, distance, diag-major scatter.
#pragma unroll
    for (int mt = 0; mt < 4; mt++) {
#pragma unroll
        for (int nt = 0; nt < 2; nt++) {
            wmma::store_matrix_sync(&patch[wid][0], cfrag[mt][nt], 16, wmma::mem_row_major);
            __syncwarp();
#pragma unroll
            for (int e = 0; e < 8; e++) {
                int idx = lane + e * 32;
                int r  = idx >> 4;
                int cc = idx & 15;
                int m = m0 + wm * 64 + mt * 16 + r;
                int n = n0 + wn * 32 + nt * 16 + cc;
                if (m < T1 && n < T2) {
                    float d2 = g_na[b * T1 + m] + g_nb[b * T2 + n] - 2.f * patch[wid][idx];
                    g_Dd[((size_t)b * NDIAG + (m + n)) * T1 + m] = sqrtf(fmaxf(d2, 0.f));
                }
            }
            __syncwarp();
        }
    }
}

// ---------------------------------------------------------------------------
// Kernel 3: per-batch DTW DP — 128 threads, 4 rows/thread, float4 smem traffic,
// rotation-prefetched coalesced float4 D loads; same recurrence/tie-breaks.
// Then the two-phase smem-staged backtrack (unchanged).
// ---------------------------------------------------------------------------
__global__ __launch_bounds__(128)
void dtw_kernel() {
    __shared__ float sdiag[3 * T1];
    __shared__ int   slo[T2];
    __shared__ int   shi[T2];
    __shared__ unsigned char chS[(T1 - SPLIT) * T2Q];
    __shared__ int s_pi, s_pj;

    int b = blockIdx.x;
    int tid = threadIdx.x;
    const float* Db = g_Dd + (size_t)b * NDIAG * T1;
    unsigned char* chb = g_ch + (size_t)b * T2Q * T1;

    bool act = (tid < T1 / 4);   // 100 active threads
    int i0 = tid * 4;

    unsigned int cacc[4] = {0u, 0u, 0u, 0u};
    const float4 Z4 = make_float4(0.f, 0.f, 0.f, 0.f);

    // Rotation prefetch (depth 4 diagonals): dpre[u] holds D[k] with k%4==u.
    float4 dpre[4];
#pragma unroll
    for (int p = 0; p < 4; p++)
        dpre[p] = act ? *(const float4*)(Db + (size_t)p * T1 + i0) : Z4;

    for (int kb = 0; kb < 1000; kb += 4) {   // k=999 has no valid cell; inert
#pragma unroll
        for (int u = 0; u < 4; u++) {
            int k = kb + u;
            float4 d4 = dpre[u];
            int kp = k + 4;
            dpre[u] = (act && kp < NDIAG) ? *(const float4*)(Db + (size_t)kp * T1 + i0) : Z4;

            float* cur = sdiag + (k % 3) * T1;
            float* prv = sdiag + ((k + 2) % 3) * T1;
            float* pp  = sdiag + ((k + 1) % 3) * T1;

            int e = k - i0;   // row r has j = e - r
            if (act && e >= 0 && e <= (T2 - 1) + 3) {
                float4 prv4 = *(const float4*)&prv[i0];
                float4 pp4  = *(const float4*)&pp[i0];
                float prvm1 = (i0 > 0) ? prv[i0 - 1] : 0.f;
                float ppm1  = (i0 > 0) ? pp[i0 - 1] : 0.f;
                float dv[4] = { d4.x, d4.y, d4.z, d4.w };
                float pv[5] = { prvm1, prv4.x, prv4.y, prv4.z, prv4.w };  // prv[i0-1..i0+3]
                float qv[4] = { ppm1, pp4.x, pp4.y, pp4.z };              // pp[i0-1..i0+2]
                float ov[4];
#pragma unroll
                for (int r = 0; r < 4; r++) {
                    int i = i0 + r;
                    int j = e - r;
                    float rr;
                    unsigned int c;
                    if (i == 0 && j == 0)      { rr = dv[r];          c = 0u; }
                    else if (i == 0)           { rr = dv[r] + pv[1];  c = 2u; }   // prv[0]
                    else if (j == 0)           { rr = dv[r] + pv[r];  c = 1u; }   // prv[i-1]
                    else {
                        float cd = qv[r];       // pp[i-1]
                        float cu = pv[r];       // prv[i-1]
                        float cl = pv[r + 1];   // prv[i]
                        rr = dv[r] + fminf(fminf(cu, cl), cd);
                        c = (cd <= cu && cd <= cl) ? 0u : ((cu <= cl) ? 1u : 2u);
                    }
                    ov[r] = rr;
                    if (j >= 0 && j < T2) {
                        cacc[r] |= c << ((j & 3) * 2);
                        if ((j & 3) == 3) {
                            chb[(j >> 2) * T1 + i] = (unsigned char)cacc[r];
                            cacc[r] = 0u;
                        }
                    }
                }
                *(float4*)&cur[i0] = make_float4(ov[0], ov[1], ov[2], ov[3]);
            }
            __syncthreads();
        }
    }

    // --- Stage TOP choice rows [SPLIT..T1) into smem
    {
        const int RT = T1 - SPLIT;
        for (int idx = tid; idx < T2Q * RT; idx += blockDim.x) {
            int jq = idx / RT;
            int o  = idx - jq * RT;
            chS[idx] = chb[jq * T1 + SPLIT + o];
        }
    }
    __syncthreads();

    // --- Backtrack phase A (rows >= SPLIT), all-smem chase
    if (tid == 0) {
        const int RT = T1 - SPLIT;
        int pi = T1 - 1, pj = T2 - 1;
        shi[pj] = pi;
        while (pi >= SPLIT) {
            slo[pj] = pi;
            int c = (chS[(pj >> 2) * RT + (pi - SPLIT)] >> ((pj & 3) * 2)) & 3;
            int ni = (c <= 1) ? pi - 1 : pi;
            int nj = (c != 1) ? pj - 1 : pj;
            if (nj != pj) shi[nj] = ni;
            pi = ni; pj = nj;
        }
        s_pi = pi; s_pj = pj;
    }
    __syncthreads();

    // --- Stage BOTTOM choice rows [0..SPLIT)
    for (int idx = tid; idx < T2Q * SPLIT; idx += blockDim.x) {
        int jq = idx / SPLIT;
        int o  = idx - jq * SPLIT;
        chS[idx] = chb[jq * T1 + o];
    }
    __syncthreads();

    // --- Backtrack phase B (rows < SPLIT)
    if (tid == 0) {
        int pi = s_pi, pj = s_pj;
        while (true) {
            slo[pj] = pi;
            if (pi == 0 && pj == 0) break;
            int c = (chS[(pj >> 2) * SPLIT + pi] >> ((pj & 3) * 2)) & 3;
            int ni = (c <= 1) ? pi - 1 : pi;
            int nj = (c != 1) ? pj - 1 : pj;
            if (nj != pj) shi[nj] = ni;
            pi = ni; pj = nj;
        }
    }
    __syncthreads();

    for (int j = tid; j < T2; j += blockDim.x) {
        g_lo[b * T2 + j] = slo[j];
        g_hi[b * T2 + j] = shi[j];
    }
}

// ---------------------------------------------------------------------------
// Kernel 4: expansion — out[b][j][:] = sum_{i=lo..hi} teacher[b][i][:]
// ---------------------------------------------------------------------------
__global__ __launch_bounds__(256)
void expand_kernel(const float* __restrict__ Tt, float* __restrict__ out) {
    int j = blockIdx.x;
    int b = blockIdx.y;
    int lo = g_lo[b * T2 + j];
    int hi = g_hi[b * T2 + j];
    int d4 = threadIdx.x;
    float4 acc = make_float4(0.f, 0.f, 0.f, 0.f);
    const float4* base = (const float4*)(Tt + (size_t)b * T1 * DIM);
    for (int i2 = lo; i2 <= hi; i2++) {
        float4 v = base[(size_t)i2 * (DIM / 4) + d4];
        acc.x += v.x; acc.y += v.y; acc.z += v.z; acc.w += v.w;
    }
    ((float4*)out)[(size_t)(b * T2 + j) * (DIM / 4) + d4] = acc;
}

// ---------------------------------------------------------------------------
// Launch — kernel launches only; same 6-launch structure as R6/R7 so the
// ncu-profiled slot stays on the GEMM.
// ---------------------------------------------------------------------------
extern "C" void kernel_launch(void* const* d_in, const int* in_sizes, int n_in,
                              void* d_out, int out_size) {
    const float* teacher = (const float*)d_in[0];  // [16,400,1024]
    const float* student = (const float*)d_in[1];  // [16,600,1024]
    float* out = (float*)d_out;                    // [16,600,1024]

    dummy_kernel<<<1, 32>>>();
    dummy_kernel<<<1, 32>>>();

    {
        int nwarps = NB * (T1 + T2);
        int nblocks = (nwarps + 7) / 8;
        norm_kernel<<<nblocks, 256>>>(teacher, student);
    }

    {
        dim3 grid((T2 + BN - 1) / BN, (T1 + BM - 1) / BM, NB);  // 5 x 4 x 16
        gemm_dist_kernel<<<grid, 256>>>(teacher, student);
    }

    dtw_kernel<<<NB, 128>>>();

    {
        dim3 grid(T2, NB);
        expand_kernel<<<grid, 256>>>(teacher, out);
    }
}

// round 10
// speedup vs baseline: 1.0855x; 1.0855x over previous
#include <cuda_runtime.h>
#include <cuda_bf16.h>
#include <math.h>
#include <stdint.h>

// Problem constants
#define NB 16
#define T1 400
#define T2 600
#define DIM 1024
#define T2Q (T2 / 4)          // 150 packed-choice bytes per row
#define SPLIT 192             // DTW backtrack staging split row
#define RPL 16                // DTW rows per lane
#define NLANES 25             // 25 * 16 = 400 rows

// ---------------------------------------------------------------------------
// Device scratch (no allocations allowed)
// ---------------------------------------------------------------------------
__device__ float g_D[NB * T1 * T2];            // distance matrix, ROW-major [b][i][j]
__device__ float g_na[NB * T1];
__device__ float g_nb[NB * T2];
__device__ int   g_lo[NB * T2];
__device__ int   g_hi[NB * T2];
__device__ unsigned char g_ch[NB * T2Q * T1];  // 2-bit DP choices [b][jq][i]

// ---------------------------------------------------------------------------
// Kernel 0: dummy — put the ncu-profiled launch (index 3) on dtw_kernel.
// ---------------------------------------------------------------------------
__global__ void dummy_kernel() {}

// ---------------------------------------------------------------------------
// Kernel 1: squared norms. One warp per row.
// ---------------------------------------------------------------------------
__global__ void norm_kernel(const float* __restrict__ T, const float* __restrict__ S) {
    int warp = (blockIdx.x * blockDim.x + threadIdx.x) >> 5;
    int lane = threadIdx.x & 31;
    const int NT = NB * T1;
    const int NS = NB * T2;
    if (warp >= NT + NS) return;
    const float* src;
    float* dst;
    if (warp < NT) { src = T + (size_t)warp * DIM;        dst = g_na + warp; }
    else           { src = S + (size_t)(warp - NT) * DIM; dst = g_nb + (warp - NT); }
    float s = 0.f;
#pragma unroll
    for (int it = 0; it < DIM / 128; it++) {
        float4 v = *(const float4*)(src + (size_t)(lane + it * 32) * 4);
        s += v.x * v.x + v.y * v.y + v.z * v.z + v.w * v.w;
    }
#pragma unroll
    for (int o = 16; o; o >>= 1) s += __shfl_xor_sync(0xFFFFFFFFu, s, o);
    if (lane == 0) *dst = s;
}

// ---------------------------------------------------------------------------
// Kernel 2: batched SIMT GEMM + distance epilogue -> ROW-major D.
// Exactly the R6 mainloop (best measured: 406us), coalesced float4 epilogue.
// BM=64, BN=128, BK=16, 256 threads, 4x8 microtile, double-buffered smem.
// ---------------------------------------------------------------------------
#define BM 64
#define BN 128
#define BK 16
#define NKT (DIM / BK)   // 64

__global__ __launch_bounds__(256)
void gemm_dist_kernel(const float* __restrict__ A, const float* __restrict__ B) {
    int b  = blockIdx.z;
    int m0 = blockIdx.y * BM;
    int n0 = blockIdx.x * BN;
    const float* Ab = A + (size_t)b * T1 * DIM;
    const float* Bb = B + (size_t)b * T2 * DIM;

    __shared__ float As[2][BK][BM];
    __shared__ float Bs[2][BK][BN];

    int tid = threadIdx.x;
    int tx = tid & 15;   // n-group (8 cols each)
    int ty = tid >> 4;   // m-group (4 rows each), 0..15

    float acc[4][8];
#pragma unroll
    for (int i = 0; i < 4; i++)
#pragma unroll
        for (int j = 0; j < 8; j++) acc[i][j] = 0.f;

    int arow = tid >> 2;
    int acol = (tid & 3) << 2;
    bool aok = (m0 + arow) < T1;
    const float* aptr = Ab + (size_t)(m0 + arow) * DIM + acol;

    int brow0 = tid >> 2;
    int brow1 = (tid + 256) >> 2;
    int bcol  = (tid & 3) << 2;
    bool bok0 = (n0 + brow0) < T2;
    bool bok1 = (n0 + brow1) < T2;
    const float* bptr0 = Bb + (size_t)(n0 + brow0) * DIM + bcol;
    const float* bptr1 = Bb + (size_t)(n0 + brow1) * DIM + bcol;

    const float4 Z = make_float4(0.f, 0.f, 0.f, 0.f);
    float4 sa, sb0, sb1;

    sa  = aok  ? *(const float4*)(aptr)  : Z;
    sb0 = bok0 ? *(const float4*)(bptr0) : Z;
    sb1 = bok1 ? *(const float4*)(bptr1) : Z;
    As[0][acol + 0][arow] = sa.x;  As[0][acol + 1][arow] = sa.y;
    As[0][acol + 2][arow] = sa.z;  As[0][acol + 3][arow] = sa.w;
    Bs[0][bcol + 0][brow0] = sb0.x; Bs[0][bcol + 1][brow0] = sb0.y;
    Bs[0][bcol + 2][brow0] = sb0.z; Bs[0][bcol + 3][brow0] = sb0.w;
    Bs[0][bcol + 0][brow1] = sb1.x; Bs[0][bcol + 1][brow1] = sb1.y;
    Bs[0][bcol + 2][brow1] = sb1.z; Bs[0][bcol + 3][brow1] = sb1.w;
    __syncthreads();

    for (int kt = 0; kt < NKT; kt++) {
        int c = kt & 1;
        if (kt + 1 < NKT) {
            const float* ap = aptr + (kt + 1) * BK;
            sa  = aok  ? *(const float4*)(ap) : Z;
            sb0 = bok0 ? *(const float4*)(bptr0 + (kt + 1) * BK) : Z;
            sb1 = bok1 ? *(const float4*)(bptr1 + (kt + 1) * BK) : Z;
        }

#pragma unroll
        for (int k = 0; k < BK; k++) {
            float4 af  = *(const float4*)&As[c][k][ty * 4];
            float4 bf0 = *(const float4*)&Bs[c][k][tx * 8];
            float4 bf1 = *(const float4*)&Bs[c][k][tx * 8 + 4];
            float ar[4] = { af.x, af.y, af.z, af.w };
            float br[8] = { bf0.x, bf0.y, bf0.z, bf0.w, bf1.x, bf1.y, bf1.z, bf1.w };
#pragma unroll
            for (int i = 0; i < 4; i++)
#pragma unroll
                for (int j = 0; j < 8; j++)
                    acc[i][j] = fmaf(ar[i], br[j], acc[i][j]);
        }

        if (kt + 1 < NKT) {
            int nc = c ^ 1;
            As[nc][acol + 0][arow] = sa.x;  As[nc][acol + 1][arow] = sa.y;
            As[nc][acol + 2][arow] = sa.z;  As[nc][acol + 3][arow] = sa.w;
            Bs[nc][bcol + 0][brow0] = sb0.x; Bs[nc][bcol + 1][brow0] = sb0.y;
            Bs[nc][bcol + 2][brow0] = sb0.z; Bs[nc][bcol + 3][brow0] = sb0.w;
            Bs[nc][bcol + 0][brow1] = sb1.x; Bs[nc][bcol + 1][brow1] = sb1.y;
            Bs[nc][bcol + 2][brow1] = sb1.z; Bs[nc][bcol + 3][brow1] = sb1.w;
            __syncthreads();
        }
    }

    // Epilogue: distance + row-major coalesced store (600 % 8 == 0 -> float4-safe)
    int n = n0 + tx * 8;
    if (n < T2) {
        float nb0 = g_nb[b * T2 + n + 0], nb1 = g_nb[b * T2 + n + 1];
        float nb2 = g_nb[b * T2 + n + 2], nb3 = g_nb[b * T2 + n + 3];
        float nb4 = g_nb[b * T2 + n + 4], nb5 = g_nb[b * T2 + n + 5];
        float nb6 = g_nb[b * T2 + n + 6], nb7 = g_nb[b * T2 + n + 7];
#pragma unroll
        for (int i = 0; i < 4; i++) {
            int m = m0 + ty * 4 + i;
            if (m >= T1) continue;
            float nam = g_na[b * T1 + m];
            float4 o0, o1;
            o0.x = sqrtf(fmaxf(nam + nb0 - 2.f * acc[i][0], 0.f));
            o0.y = sqrtf(fmaxf(nam + nb1 - 2.f * acc[i][1], 0.f));
            o0.z = sqrtf(fmaxf(nam + nb2 - 2.f * acc[i][2], 0.f));
            o0.w = sqrtf(fmaxf(nam + nb3 - 2.f * acc[i][3], 0.f));
            o1.x = sqrtf(fmaxf(nam + nb4 - 2.f * acc[i][4], 0.f));
            o1.y = sqrtf(fmaxf(nam + nb5 - 2.f * acc[i][5], 0.f));
            o1.z = sqrtf(fmaxf(nam + nb6 - 2.f * acc[i][6], 0.f));
            o1.w = sqrtf(fmaxf(nam + nb7 - 2.f * acc[i][7], 0.f));
            float* dst = g_D + ((size_t)(b * T1 + m)) * T2 + n;
            *(float4*)(dst)     = o0;
            *(float4*)(dst + 4) = o1;
        }
    }
}

// ---------------------------------------------------------------------------
// Kernel 3: warp-per-batch register DTW. Warp 0 runs the whole wavefront in
// registers (16 rows/lane, 25 active lanes, shfl for cross-lane deps, no
// barriers). Recurrence/tie-breaks byte-identical to all passing rounds.
// Then all 4 warps run the two-phase smem-staged backtrack.
// ---------------------------------------------------------------------------

// One anti-diagonal step. PREV = R at k-1, PPW = R at k-2 (overwritten with k).
// All indices static after unroll: u is a literal, rows processed descending.
#define DTW_STEP(PREV, PPW, U) do {                                              \
    float sprev = __shfl_up_sync(0xFFFFFFFFu, PREV[RPL - 1], 1);                 \
    float spp   = __shfl_up_sync(0xFFFFFFFFu, PPW[RPL - 1], 1);                  \
    int e = kb + (U) - i0;                                                       \
_Pragma("unroll")                                                                \
    for (int rr_ = RPL - 1; rr_ >= 0; rr_--) {                                   \
        const int s_   = ((U) - rr_) & 7;                                        \
        const int comp = s_ & 3;                                                 \
        const int par  = s_ >> 2;                                                \
        int j = e - rr_;                                                         \
        int i = i0 + rr_;                                                        \
        if (comp == 0) {                                                         \
            if (act && j >= 0 && j + 8 <= T2)                                    \
                dbuf[par ^ 1][rr_] = *(const float4*)(Db + (size_t)i * T2 + j + 4); \
        }                                                                        \
        float d = (comp == 0) ? dbuf[par][rr_].x :                               \
                  (comp == 1) ? dbuf[par][rr_].y :                               \
                  (comp == 2) ? dbuf[par][rr_].z : dbuf[par][rr_].w;             \
        bool valid = act && (j >= 0) && (j < T2);                                \
        float cu_ = (rr_ == 0) ? sprev : PREV[(rr_ > 0) ? rr_ - 1 : 0];          \
        float cd_ = (rr_ == 0) ? spp   : PPW[(rr_ > 0) ? rr_ - 1 : 0];           \
        float cl_ = PREV[rr_];                                                   \
        float rrv; unsigned int c;                                               \
        if (i == 0) { rrv = (j == 0) ? d : d + PREV[0]; c = (j == 0) ? 0u : 2u; }\
        else if (j == 0) { rrv = d + cu_; c = 1u; }                              \
        else {                                                                   \
            rrv = d + fminf(fminf(cu_, cl_), cd_);                               \
            c = (cd_ <= cu_ && cd_ <= cl_) ? 0u : ((cu_ <= cl_) ? 1u : 2u);      \
        }                                                                        \
        if (valid) {                                                             \
            PPW[rr_] = rrv;                                                      \
            cacc[rr_] |= c << (comp * 2);                                        \
            if (comp == 3) {                                                     \
                chb[(j >> 2) * T1 + i] = (unsigned char)cacc[rr_];               \
                cacc[rr_] = 0u;                                                  \
            }                                                                    \
        }                                                                        \
    }                                                                            \
} while (0)

__global__ __launch_bounds__(128, 1)
void dtw_kernel() {
    __shared__ int slo[T2];
    __shared__ int shi[T2];
    __shared__ unsigned char chS[(T1 - SPLIT) * T2Q];  // 31200 B, reused for bottom half
    __shared__ int s_pi, s_pj;

    int b = blockIdx.x;
    int tid = threadIdx.x;
    const float* Db = g_D + (size_t)b * T1 * T2;
    unsigned char* chb = g_ch + (size_t)b * T2Q * T1;

    if (tid < 32) {
        int lane = tid;
        bool act = (lane < NLANES);
        int i0 = lane * RPL;

        float rA[RPL], rB[RPL];
        float4 dbuf[2][RPL];
        unsigned int cacc[RPL];
#pragma unroll
        for (int r = 0; r < RPL; r++) {
            rA[r] = 0.f; rB[r] = 0.f; cacc[r] = 0u;
            dbuf[0][r] = make_float4(0.f, 0.f, 0.f, 0.f);
            dbuf[1][r] = make_float4(0.f, 0.f, 0.f, 0.f);
        }
        // preload block 0 (j = 0..3) per row
#pragma unroll
        for (int r = 0; r < RPL; r++)
            if (act) dbuf[0][r] = *(const float4*)(Db + (size_t)(i0 + r) * T2);

        // k = kb+u; roles alternate: even u -> prev=rA, write rB; odd -> swap.
        for (int kb = 0; kb < 1000; kb += 8) {
            DTW_STEP(rA, rB, 0);
            DTW_STEP(rB, rA, 1);
            DTW_STEP(rA, rB, 2);
            DTW_STEP(rB, rA, 3);
            DTW_STEP(rA, rB, 4);
            DTW_STEP(rB, rA, 5);
            DTW_STEP(rA, rB, 6);
            DTW_STEP(rB, rA, 7);
        }
    }
    __syncthreads();

    // --- Stage TOP choice rows [SPLIT..T1) into smem
    {
        const int RT = T1 - SPLIT;
        for (int idx = tid; idx < T2Q * RT; idx += blockDim.x) {
            int jq = idx / RT;
            int o  = idx - jq * RT;
            chS[idx] = chb[jq * T1 + SPLIT + o];
        }
    }
    __syncthreads();

    // --- Backtrack phase A (rows >= SPLIT), all-smem chase
    if (tid == 0) {
        const int RT = T1 - SPLIT;
        int pi = T1 - 1, pj = T2 - 1;
        shi[pj] = pi;
        while (pi >= SPLIT) {
            slo[pj] = pi;
            int c = (chS[(pj >> 2) * RT + (pi - SPLIT)] >> ((pj & 3) * 2)) & 3;
            int ni = (c <= 1) ? pi - 1 : pi;
            int nj = (c != 1) ? pj - 1 : pj;
            if (nj != pj) shi[nj] = ni;
            pi = ni; pj = nj;
        }
        s_pi = pi; s_pj = pj;
    }
    __syncthreads();

    // --- Stage BOTTOM choice rows [0..SPLIT)
    for (int idx = tid; idx < T2Q * SPLIT; idx += blockDim.x) {
        int jq = idx / SPLIT;
        int o  = idx - jq * SPLIT;
        chS[idx] = chb[jq * T1 + o];
    }
    __syncthreads();

    // --- Backtrack phase B (rows < SPLIT)
    if (tid == 0) {
        int pi = s_pi, pj = s_pj;
        while (true) {
            slo[pj] = pi;
            if (pi == 0 && pj == 0) break;
            int c = (chS[(pj >> 2) * SPLIT + pi] >> ((pj & 3) * 2)) & 3;
            int ni = (c <= 1) ? pi - 1 : pi;
            int nj = (c != 1) ? pj - 1 : pj;
            if (nj != pj) shi[nj] = ni;
            pi = ni; pj = nj;
        }
    }
    __syncthreads();

    for (int j = tid; j < T2; j += blockDim.x) {
        g_lo[b * T2 + j] = slo[j];
        g_hi[b * T2 + j] = shi[j];
    }
}

// ---------------------------------------------------------------------------
// Kernel 4: expansion — out[b][j][:] = sum_{i=lo..hi} teacher[b][i][:]
// ---------------------------------------------------------------------------
__global__ __launch_bounds__(256)
void expand_kernel(const float* __restrict__ Tt, float* __restrict__ out) {
    int j = blockIdx.x;
    int b = blockIdx.y;
    int lo = g_lo[b * T2 + j];
    int hi = g_hi[b * T2 + j];
    int d4 = threadIdx.x;
    float4 acc = make_float4(0.f, 0.f, 0.f, 0.f);
    const float4* base = (const float4*)(Tt + (size_t)b * T1 * DIM);
    for (int i2 = lo; i2 <= hi; i2++) {
        float4 v = base[(size_t)i2 * (DIM / 4) + d4];
        acc.x += v.x; acc.y += v.y; acc.z += v.z; acc.w += v.w;
    }
    ((float4*)out)[(size_t)(b * T2 + j) * (DIM / 4) + d4] = acc;
}

// ---------------------------------------------------------------------------
// Launch — kernel launches only. Profiled launch = index 3 = dtw_kernel.
// ---------------------------------------------------------------------------
extern "C" void kernel_launch(void* const* d_in, const int* in_sizes, int n_in,
                              void* d_out, int out_size) {
    const float* teacher = (const float*)d_in[0];  // [16,400,1024]
    const float* student = (const float*)d_in[1];  // [16,600,1024]
    float* out = (float*)d_out;                    // [16,600,1024]

    dummy_kernel<<<1, 32>>>();

    {
        int nwarps = NB * (T1 + T2);
        int nblocks = (nwarps + 7) / 8;
        norm_kernel<<<nblocks, 256>>>(teacher, student);
    }

    {
        dim3 grid((T2 + BN - 1) / BN, (T1 + BM - 1) / BM, NB);
        gemm_dist_kernel<<<grid, 256>>>(teacher, student);
    }

    dtw_kernel<<<NB, 128>>>();

    {
        dim3 grid(T2, NB);
        expand_kernel<<<grid, 256>>>(teacher, out);
    }
}